// round 17
// baseline (speedup 1.0000x reference)
#include <cuda_runtime.h>
#include <math.h>

#define THREADS 256
#define NCH 24            // 768 / 32
#define EDIM 768

// ---- single fp32 staging ----
#define ST_C 0            // fp32 C: 128 x 128B = 16KB
#define ST_E 16384        // fp32 E: 16KB
#define ST_W 32768        // fp32 w0: 10 rows x 128B = 1280B
// ---- double-buffered bf16 tiles (offsets relative to buffer base) ----
#define TA_HI 0           // 128 x 32 bf16, 64B rows, SW64 = 8KB
#define TA_LO 8192
#define TB_HI 16384
#define TB_LO 24576
#define TWC_HI 32768      // 8 x 32 bf16 = 512B (rows 5..7 zero)
#define TWC_LO 33280
#define TWE_HI 33792
#define TWE_LO 34304
#define T0_OFF 34816
#define T1_OFF 69632
// ---- misc ----
#define O_ICN 104448
#define O_IEN 104960
#define O_SSUM 105472
#define SMEM_BYTES 105504
// aliases in staging region (used after GEMM completes)
#define O_RED 0           // float2[128][8]
#define O_PCS 16384
#define O_PES 24576

#define SW64(o) ((o) ^ (((o) >> 3) & 0x30u))

static __device__ __forceinline__ unsigned smem_u32(const void* p) {
    unsigned a;
    asm("{ .reg .u64 t; cvta.to.shared.u64 t, %1; cvt.u32.u64 %0, t; }" : "=r"(a) : "l"(p));
    return a;
}
static __device__ __forceinline__ void cp16(unsigned dst, const void* src) {
    asm volatile("cp.async.cg.shared.global [%0], [%1], 16;" :: "r"(dst), "l"(src));
}
static __device__ __forceinline__ void cp_commit() {
    asm volatile("cp.async.commit_group;" ::: "memory");
}
static __device__ __forceinline__ void cp_wait0() {
    asm volatile("cp.async.wait_group 0;" ::: "memory");
}
static __device__ __forceinline__ void ldsm4(unsigned& r0, unsigned& r1, unsigned& r2, unsigned& r3,
                                             unsigned a) {
    asm volatile("ldmatrix.sync.aligned.m8n8.x4.shared.b16 {%0,%1,%2,%3}, [%4];"
                 : "=r"(r0), "=r"(r1), "=r"(r2), "=r"(r3) : "r"(a));
}
static __device__ __forceinline__ void ldsm2(unsigned& r0, unsigned& r1, unsigned a) {
    asm volatile("ldmatrix.sync.aligned.m8n8.x2.shared.b16 {%0,%1}, [%2];"
                 : "=r"(r0), "=r"(r1) : "r"(a));
}
static __device__ __forceinline__ void mma16816(float* c, const unsigned* a, const unsigned* b) {
    asm volatile("mma.sync.aligned.m16n8k16.row.col.f32.bf16.bf16.f32 "
                 "{%0,%1,%2,%3}, {%4,%5,%6,%7}, {%8,%9}, {%0,%1,%2,%3};"
                 : "+f"(c[0]), "+f"(c[1]), "+f"(c[2]), "+f"(c[3])
                 : "r"(a[0]), "r"(a[1]), "r"(a[2]), "r"(a[3]), "r"(b[0]), "r"(b[1]));
}
// A-operand (m16k16 row-major) ldmatrix address, 64B rows, SW64 (tile-relative)
static __device__ __forceinline__ unsigned asw(int row0, int kb, int lane) {
    const int m = lane >> 3, r = lane & 7;
    const int row = row0 + ((m & 1) << 3) + r;
    const int byte = kb + ((m >> 1) << 4);
    return SW64((unsigned)(row * 64 + byte));
}
// B-operand ldmatrix address
static __device__ __forceinline__ unsigned bsw(int n0, int kb, int lane) {
    const int m = lane >> 3, r = lane & 7;
    const int row = n0 + ((m >> 1) << 3) + r;
    const int byte = kb + ((m & 1) << 4);
    return SW64((unsigned)(row * 64 + byte));
}
// fp32x4 -> hi bf16x4 + residual-lo bf16x4, accumulate sum of squares
static __device__ __forceinline__ void cvt_store(char* hip, char* lop, float4 v, float& sq) {
    sq += v.x * v.x + v.y * v.y + v.z * v.z + v.w * v.w;
    unsigned h01, h23, l01, l23;
    asm("cvt.rn.bf16x2.f32 %0, %2, %1;" : "=r"(h01) : "f"(v.x), "f"(v.y));
    asm("cvt.rn.bf16x2.f32 %0, %2, %1;" : "=r"(h23) : "f"(v.z), "f"(v.w));
    float f0 = __uint_as_float(h01 << 16);
    float f1 = __uint_as_float(h01 & 0xffff0000u);
    float f2 = __uint_as_float(h23 << 16);
    float f3 = __uint_as_float(h23 & 0xffff0000u);
    float r0 = v.x - f0, r1 = v.y - f1, r2 = v.z - f2, r3 = v.w - f3;
    asm("cvt.rn.bf16x2.f32 %0, %2, %1;" : "=r"(l01) : "f"(r0), "f"(r1));
    asm("cvt.rn.bf16x2.f32 %0, %2, %1;" : "=r"(l23) : "f"(r2), "f"(r3));
    *(uint2*)hip = make_uint2(h01, h23);
    *(uint2*)lop = make_uint2(l01, l23);
}

// stage one K=32 chunk (C, E, w0) into the single staging buffer
static __device__ __forceinline__ void stage_chunk(unsigned sb, const float* Cb,
                                                   const float* Eb, const float* w0,
                                                   int cb, int tid) {
    #pragma unroll
    for (int j = 0; j < 4; ++j) {
        const int o = tid + 256 * j;                 // 0..1023
        const int row = o >> 3, q = o & 7;
        cp16(sb + ST_C + o * 16, Cb + row * EDIM + cb + q * 4);
        cp16(sb + ST_E + o * 16, Eb + row * EDIM + cb + q * 4);
    }
    if (tid < 80) {
        const int r = tid >> 3, q = tid & 7;         // 5 c-rows then 5 e-rows
        cp16(sb + ST_W + tid * 16, w0 + (r % 5) * 1536 + (r / 5) * 768 + cb + q * 4);
    }
    cp_commit();
}

// convert a subset of row-iterations of the staged chunk into tile buffer t_off
static __device__ __forceinline__ void convert_rows(char* smem, int t_off, int i0, int i1,
                                                    int cr, int cq, float* sqC, float* sqE) {
    char* T = smem + t_off;
    #pragma unroll
    for (int i = i0; i < i1; ++i) {
        const int row = cr + 32 * i;
        const int qq = (cq + row) & 7;               // quad rotation: conflict-free LDS
        float4 cv = *(const float4*)(smem + ST_C + row * 128 + qq * 16);
        float4 ev = *(const float4*)(smem + ST_E + row * 128 + qq * 16);
        const unsigned o = SW64((unsigned)(row * 64 + qq * 8));
        cvt_store(T + TA_HI + o, T + TA_LO + o, cv, sqC[i]);
        cvt_store(T + TB_HI + o, T + TB_LO + o, ev, sqE[i]);
    }
}
static __device__ __forceinline__ void convert_w0(char* smem, int t_off, int tid) {
    if (tid < 80) {
        const int r = tid >> 3, q = tid & 7;
        float4 wv = *(const float4*)(smem + ST_W + tid * 16);
        const int half = r / 5, rr = r % 5;
        char* hb = smem + t_off + (half ? TWE_HI : TWC_HI);
        float dmy = 0.f;
        const unsigned o = SW64((unsigned)(rr * 64 + q * 8));
        cvt_store(hb + o, hb + 512 + o, wv, dmy);
    }
}

// one k16 step (kb) of the 3-split main GEMM
static __device__ __forceinline__ void gemm_main_s(float accD[2][8][4], unsigned tb, int kb,
                                                   int mrow, int ncol, int lane) {
    unsigned Ah[8], Ax[8], Bf[16];
    ldsm4(Ah[0], Ah[1], Ah[2], Ah[3], tb + TA_HI + asw(mrow, kb, lane));
    ldsm4(Ah[4], Ah[5], Ah[6], Ah[7], tb + TA_HI + asw(mrow + 16, kb, lane));
    #pragma unroll
    for (int pq = 0; pq < 4; ++pq)
        ldsm4(Bf[4*pq], Bf[4*pq+1], Bf[4*pq+2], Bf[4*pq+3],
              tb + TB_HI + bsw(ncol + 16 * pq, kb, lane));
    #pragma unroll
    for (int mt = 0; mt < 2; ++mt)
        #pragma unroll
        for (int nt = 0; nt < 8; ++nt)
            mma16816(accD[mt][nt], Ah + 4 * mt, Bf + (nt >> 1) * 4 + (nt & 1) * 2);
    ldsm4(Ax[0], Ax[1], Ax[2], Ax[3], tb + TA_LO + asw(mrow, kb, lane));
    ldsm4(Ax[4], Ax[5], Ax[6], Ax[7], tb + TA_LO + asw(mrow + 16, kb, lane));
    #pragma unroll
    for (int mt = 0; mt < 2; ++mt)
        #pragma unroll
        for (int nt = 0; nt < 8; ++nt)
            mma16816(accD[mt][nt], Ax + 4 * mt, Bf + (nt >> 1) * 4 + (nt & 1) * 2);
    #pragma unroll
    for (int pq = 0; pq < 4; ++pq)
        ldsm4(Bf[4*pq], Bf[4*pq+1], Bf[4*pq+2], Bf[4*pq+3],
              tb + TB_LO + bsw(ncol + 16 * pq, kb, lane));
    #pragma unroll
    for (int mt = 0; mt < 2; ++mt)
        #pragma unroll
        for (int nt = 0; nt < 8; ++nt)
            mma16816(accD[mt][nt], Ah + 4 * mt, Bf + (nt >> 1) * 4 + (nt & 1) * 2);
}

// w0 projection for both k16 steps (warps 0-3: p_c from A; 4-7: p_e from B)
static __device__ __forceinline__ void gemm_proj(float accP[2][4], unsigned tb, int mrow,
                                                 int isC, int lane) {
    const unsigned phi = tb + (isC ? TA_HI : TB_HI);
    const unsigned plo = phi + 8192;
    const unsigned whi = tb + (isC ? TWC_HI : TWE_HI);
    const unsigned wlo = whi + 512;
    #pragma unroll
    for (int s = 0; s < 2; ++s) {
        const int kb = s * 32;
        unsigned Ph[8], Pl[8], W[4];
        ldsm4(Ph[0], Ph[1], Ph[2], Ph[3], phi + asw(mrow, kb, lane));
        ldsm4(Ph[4], Ph[5], Ph[6], Ph[7], phi + asw(mrow + 16, kb, lane));
        ldsm4(Pl[0], Pl[1], Pl[2], Pl[3], plo + asw(mrow, kb, lane));
        ldsm4(Pl[4], Pl[5], Pl[6], Pl[7], plo + asw(mrow + 16, kb, lane));
        ldsm2(W[0], W[1], whi + bsw(0, kb, lane & 15));
        ldsm2(W[2], W[3], wlo + bsw(0, kb, lane & 15));
        mma16816(accP[0], Ph,     W);
        mma16816(accP[1], Ph + 4, W);
        mma16816(accP[0], Pl,     W);
        mma16816(accP[1], Pl + 4, W);
        mma16816(accP[0], Ph,     W + 2);
        mma16816(accP[1], Ph + 4, W + 2);
    }
}

__global__ __launch_bounds__(THREADS, 2)
void som_mma_kernel(const float* __restrict__ ctx,
                    const float* __restrict__ w0, const float* __restrict__ b0,
                    const float* __restrict__ w1, const float* __restrict__ b1,
                    const float* __restrict__ w2, const float* __restrict__ b2,
                    const float* __restrict__ w3, const float* __restrict__ b3,
                    const float* __restrict__ w4, const float* __restrict__ b4,
                    const float* __restrict__ w5, const float* __restrict__ b5,
                    const float* __restrict__ w6, const float* __restrict__ b6,
                    float* __restrict__ out)
{
    extern __shared__ char smem[];
    const unsigned sb = smem_u32(smem);
    float* icn  = (float*)(smem + O_ICN);
    float* ien  = (float*)(smem + O_IEN);
    float* ssum = (float*)(smem + O_SSUM);

    const int tid  = threadIdx.x;
    const int lane = tid & 31;
    const int wid  = tid >> 5;
    const int p    = blockIdx.x;

    const float* Cb = ctx + (size_t)p * (2 * 128 * EDIM);
    const float* Eb = Cb + 128 * EDIM;

    // zero w0 tile pads in BOTH tile buffers (rows 5..7; never written again)
    {
        const int half = tid >> 7, r = tid & 127;    // 2 x 2KB regions
        *(uint4*)(smem + (half ? T1_OFF : T0_OFF) + TWC_HI + r * 16) =
            make_uint4(0u, 0u, 0u, 0u);
    }

    const int cr = tid >> 3, cq = tid & 7;
    const int mw = wid & 3, nw = wid >> 2;
    const int mrow = mw * 32, ncol = nw * 64;
    const int g = lane >> 2, t = lane & 3;

    float accD[2][8][4];
    float accP[2][4];
    #pragma unroll
    for (int mt = 0; mt < 2; ++mt) {
        #pragma unroll
        for (int nt = 0; nt < 8; ++nt)
            #pragma unroll
            for (int k = 0; k < 4; ++k) accD[mt][nt][k] = 0.f;
        #pragma unroll
        for (int k = 0; k < 4; ++k) accP[mt][k] = 0.f;
    }
    float sqC[4] = {0.f, 0.f, 0.f, 0.f};
    float sqE[4] = {0.f, 0.f, 0.f, 0.f};

    // ---- prologue: stage + convert chunk 0 into T0, then stage chunk 1 ----
    stage_chunk(sb, Cb, Eb, w0, 0, tid);
    cp_wait0();
    __syncthreads();                       // staging visible (also covers pad zeroing)
    convert_rows(smem, T0_OFF, 0, 4, cr, cq, sqC, sqE);
    convert_w0(smem, T0_OFF, tid);
    __syncthreads();                       // staging drained; T0 ready
    stage_chunk(sb, Cb, Eb, w0, 32, tid);

    for (int c = 0; c < NCH; ++c) {
        const unsigned tcur    = sb + ((c & 1) ? T1_OFF : T0_OFF);
        const int      tnx_off = ((c + 1) & 1) ? T1_OFF : T0_OFF;

        if (c + 1 < NCH) cp_wait0();       // staging[c+1] landed
        __syncthreads();                   // visible to all; prev proj reads of tnx done

        // interleave: convert(c+1) woven between the k-steps of GEMM(c)
        if (c + 1 < NCH) convert_rows(smem, tnx_off, 0, 2, cr, cq, sqC, sqE);
        gemm_main_s(accD, tcur, 0, mrow, ncol, lane);
        if (c + 1 < NCH) {
            convert_rows(smem, tnx_off, 2, 4, cr, cq, sqC, sqE);
            convert_w0(smem, tnx_off, tid);
        }
        gemm_main_s(accD, tcur, 32, mrow, ncol, lane);

        __syncthreads();                   // staging drained by convert
        if (c + 2 < NCH) stage_chunk(sb, Cb, Eb, w0, (c + 2) * 32, tid);

        gemm_proj(accP, tcur, mrow, (wid < 4) ? 1 : 0, lane);
    }

    // ---- norm reduction over 8-lane row groups ----
    #pragma unroll
    for (int i = 0; i < 4; ++i) {
        float a = sqC[i], b = sqE[i];
        #pragma unroll
        for (int off = 1; off < 8; off <<= 1) {
            a += __shfl_xor_sync(0xffffffffu, a, off);
            b += __shfl_xor_sync(0xffffffffu, b, off);
        }
        if (cq == 0) {
            const int row = cr + 32 * i;
            icn[row] = rsqrtf(a);
            ien[row] = rsqrtf(b);
        }
    }
    __syncthreads();   // all tile/staging reads done; norms visible; aliasing safe

    // ---- argmax: (value, lower-index-wins) == first-occurrence semantics ----
    float iev[16];
    #pragma unroll
    for (int nt = 0; nt < 8; ++nt) {
        iev[nt*2]     = ien[ncol + nt * 8 + 2 * t];
        iev[nt*2 + 1] = ien[ncol + nt * 8 + 2 * t + 1];
    }
    float2* red = (float2*)(smem + O_RED);
    const int slot = nw * 4 + t;
    #pragma unroll
    for (int h = 0; h < 4; ++h) {
        const int mt = h >> 1, up = h & 1;
        const int row = mrow + mt * 16 + up * 8 + g;
        float best = -3.402823466e38f;
        int   bi = 1 << 30;
        #pragma unroll
        for (int nt = 0; nt < 8; ++nt) {
            const float v0 = accD[mt][nt][up * 2]     * iev[nt*2];
            const float v1 = accD[mt][nt][up * 2 + 1] * iev[nt*2 + 1];
            const int c0 = ncol + nt * 8 + 2 * t;
            if (v0 > best || (v0 == best && c0 < bi)) { best = v0; bi = c0; }
            if (v1 > best || (v1 == best && c0 + 1 < bi)) { best = v1; bi = c0 + 1; }
        }
        red[row * 8 + slot] = make_float2(best, __int_as_float(bi));
    }

    // ---- write scaled p_c / p_e ----
    {
        float* dst = (wid < 4) ? (float*)(smem + O_PCS) : (float*)(smem + O_PES);
        const float* inv = (wid < 4) ? icn : ien;
        const int j0 = 2 * t, j1 = 2 * t + 1;
        #pragma unroll
        for (int mt = 0; mt < 2; ++mt) {
            const int r0 = mrow + mt * 16 + g, r1 = r0 + 8;
            if (j0 < 5) {
                dst[r0 * 8 + j0] = accP[mt][0] * inv[r0];
                dst[r1 * 8 + j0] = accP[mt][2] * inv[r1];
            }
            if (j1 < 5) {
                dst[r0 * 8 + j1] = accP[mt][1] * inv[r0];
                dst[r1 * 8 + j1] = accP[mt][3] * inv[r1];
            }
        }
    }
    __syncthreads();

    // ---- per-row MLP + block sum ----
    const float* pcs = (const float*)(smem + O_PCS);
    const float* pes = (const float*)(smem + O_PES);
    float partial = 0.f;
    if (tid < 128) {
        const int l = tid;
        float best = -3.402823466e38f;
        int   bi = 1 << 30;
        #pragma unroll
        for (int s2 = 0; s2 < 8; ++s2) {
            const float2 v = red[l * 8 + s2];
            const int cc = __float_as_int(v.y);
            if (v.x > best || (v.x == best && cc < bi)) { best = v.x; bi = cc; }
        }
        float h0[5];
        #pragma unroll
        for (int j = 0; j < 5; ++j)
            h0[j] = tanhf(pcs[l * 8 + j] + pes[bi * 8 + j] + __ldg(b0 + j));
        float s0 = __ldg(b1 + 0), s1 = __ldg(b1 + 1);
        #pragma unroll
        for (int j = 0; j < 5; ++j) {
            s0 += __ldg(w1 + j)     * h0[j];
            s1 += __ldg(w1 + 5 + j) * h0[j];
        }
        float h10 = tanhf(s0), h11 = tanhf(s1);
        float z = tanhf(__ldg(w2) * h10 + __ldg(w2 + 1) * h11 + __ldg(b2));
        z = tanhf(__ldg(w3) * z + __ldg(b3));
        z = tanhf(__ldg(w4) * z + __ldg(b4));
        z = tanhf(__ldg(w5) * z + __ldg(b5));
        partial = __ldg(w6) * z + __ldg(b6);
    }
    #pragma unroll
    for (int off = 16; off; off >>= 1)
        partial += __shfl_xor_sync(0xffffffffu, partial, off);
    if (lane == 0) ssum[wid] = partial;
    __syncthreads();
    if (tid == 0) {
        float tot = 0.f;
        #pragma unroll
        for (int w = 0; w < 8; ++w) tot += ssum[w];
        out[p] = tot;
    }
}

extern "C" void kernel_launch(void* const* d_in, const int* in_sizes, int n_in,
                              void* d_out, int out_size)
{
    const float* ctx = (const float*)d_in[0];
    const float* w0 = (const float*)d_in[1];  const float* b0 = (const float*)d_in[2];
    const float* w1 = (const float*)d_in[3];  const float* b1 = (const float*)d_in[4];
    const float* w2 = (const float*)d_in[5];  const float* b2 = (const float*)d_in[6];
    const float* w3 = (const float*)d_in[7];  const float* b3 = (const float*)d_in[8];
    const float* w4 = (const float*)d_in[9];  const float* b4 = (const float*)d_in[10];
    const float* w5 = (const float*)d_in[11]; const float* b5 = (const float*)d_in[12];
    const float* w6 = (const float*)d_in[13]; const float* b6 = (const float*)d_in[14];
    float* out = (float*)d_out;

    cudaFuncSetAttribute(som_mma_kernel,
                         cudaFuncAttributeMaxDynamicSharedMemorySize, SMEM_BYTES);
    som_mma_kernel<<<1024, THREADS, SMEM_BYTES>>>(
        ctx, w0, b0, w1, b1, w2, b2, w3, b3, w4, b4, w5, b5, w6, b6, out);
}